// round 6
// baseline (speedup 1.0000x reference)
#include <cuda_runtime.h>
#include <math.h>

#define B 128
#define C 6
#define H 224
#define W 224
#define HWSZ (H*W)          // 50176
#define HW4 (HWSZ/4)        // 12544
#define POOL 7
#define NS (POOL*POOL)      // 49
#define BC (B*C)            // 768
#define CS (C*NS)           // 294
#define FEAT (3*C)          // 18
#define W4 (W/4)            // 56 float4 per row

__device__ float g_pooled[BC * NS];

__constant__ float c_prior[36] = {
    1.0f,  0.0f,  0.6f,  0.0f, -2.0f, 0.0f,
    0.0f,  1.0f,  0.6f,  0.0f,  0.0f, 0.0f,
    0.1f,  0.1f,  0.5f,  0.0f,  0.0f, 0.0f,
    0.0f,  0.0f,  0.0f,  1.0f,  0.0f, 0.0f,
    0.0f,  0.0f,  0.0f,  0.0f,  1.0f, 0.2f,
    0.0f, -0.6f, -0.6f, -0.6f,  0.6f, 1.0f
};
__constant__ float c_sign[6] = {1.f, -1.f, 1.f, -1.f, 1.f, 1.f};

__device__ __forceinline__ float tanh_fast(float x) {
    float y;
    asm("tanh.approx.f32 %0, %1;" : "=f"(y) : "f"(x));
    return y;
}

// ---------------------------------------------------------------------------
// Kernel 1: per-(b,c) channel, two-pass over L2. 256 thr, 6 blocks/SM
// (888 slots >= 768 blocks -> single wave; phases overlap across blocks).
// ---------------------------------------------------------------------------
__global__ __launch_bounds__(256, 6)
void gate_pool_kernel(const float* __restrict__ x)
{
    __shared__ float ra[8], rb[8];
    __shared__ float s_inv, s_ofs;

    const int bc = blockIdx.x;
    const float* __restrict__ xc = x + (size_t)bc * HWSZ;
    const float4* __restrict__ xin = (const float4*)xc;

    // ---- pass 1: stats (stream 200KB from DRAM) ----
    float sum = 0.f, sq = 0.f;
    #pragma unroll 7
    for (int i = threadIdx.x; i < HW4; i += 256) {
        float4 v = xin[i];
        sum += (v.x + v.y) + (v.z + v.w);
        sq  += (v.x*v.x + v.y*v.y) + (v.z*v.z + v.w*v.w);
    }

    const int warp = threadIdx.x >> 5, lane = threadIdx.x & 31;
    #pragma unroll
    for (int o = 16; o; o >>= 1) {
        sum += __shfl_down_sync(0xffffffffu, sum, o);
        sq  += __shfl_down_sync(0xffffffffu, sq,  o);
    }
    if (lane == 0) { ra[warp] = sum; rb[warp] = sq; }
    __syncthreads();
    if (warp == 0) {
        sum = (lane < 8) ? ra[lane] : 0.f;
        sq  = (lane < 8) ? rb[lane] : 0.f;
        #pragma unroll
        for (int o = 4; o; o >>= 1) {
            sum += __shfl_down_sync(0xffffffffu, sum, o);
            sq  += __shfl_down_sync(0xffffffffu, sq,  o);
        }
        if (lane == 0) {
            const float invN = 1.0f / (float)HWSZ;
            float mean = sum * invN;
            float var = (sq - sum * sum * invN) * (1.0f / (float)(HWSZ - 1));
            var = fmaxf(var, 0.0f);
            float inv_std = 1.0f / (sqrtf(var) + 1e-5f);  // tanh arg = (x-mean)/std
            s_inv = inv_std;
            s_ofs = -mean * inv_std;
        }
    }
    __syncthreads();
    const float s2 = s_inv, o2 = s_ofs;

    // ---- pass 2: gate + pool (L2-resident re-read, coalesced) ----
    const int sub = lane >> 3;      // row within 4-row group
    const int c4  = lane & 7;       // float4 within 128B row chunk
    for (int win = warp; win < NS; win += 8) {
        const int py = win / POOL, px = win - py * POOL;
        const float4* __restrict__ base =
            (const float4*)(xc + (py * 32 + sub) * W + px * 32) + c4;
        float acc = 0.f;
        #pragma unroll
        for (int r = 0; r < 8; ++r) {
            float4 v = base[r * W];   // rows sub, sub+4, ..., sub+28
            acc += tanh_fast(fmaf(v.x, s2, o2));
            acc += tanh_fast(fmaf(v.y, s2, o2));
            acc += tanh_fast(fmaf(v.z, s2, o2));
            acc += tanh_fast(fmaf(v.w, s2, o2));
        }
        #pragma unroll
        for (int o = 16; o; o >>= 1) acc += __shfl_down_sync(0xffffffffu, acc, o);
        if (lane == 0) g_pooled[bc * NS + win] = acc * (1.0f / 2048.0f) + 0.5f;
    }
}

// ---------------------------------------------------------------------------
// Kernel 2 (fused): graph mixing + feature pooling + structured upsample.
// 448 threads: thread = (segment s in 0..7, float4-column c4 in 0..55).
// Within a segment (y0,y1) are constant and fy is a compile-time constant
// per unrolled row -> inner loop is 4 FMA + 1 STG.128 per 16B.
// ---------------------------------------------------------------------------
__global__ __launch_bounds__(448)
void graph_upsample_kernel(const float* __restrict__ P_delta,
                           float* __restrict__ feat_out,
                           float* __restrict__ out)
{
    __shared__ float xs[CS], sal[CS], tmp[NS];
    __shared__ float Pcol[C], smean[C];
    __shared__ __align__(16) float g[52];
    __shared__ __align__(16) float4 hr4[POOL * W4];   // 7 x 56 float4

    const int bc = blockIdx.x;
    const int b = bc / C, d = bc - b * C;
    const int t = threadIdx.x;

    // ---- tiny graph mixing (recomputed per channel-block) ----
    for (int i = t; i < CS; i += 448) xs[i] = g_pooled[b * CS + i];
    if (t < C) Pcol[t] = c_prior[t * 6 + d] + 0.2f * tanhf(P_delta[t * 6 + d]);
    __syncthreads();

    if (t < C) {
        float m = 0.f;
        #pragma unroll
        for (int s = 0; s < NS; ++s) m += xs[t * NS + s];
        smean[t] = m * (1.0f / (float)NS);
    }
    __syncthreads();

    if (t < CS) {
        const int cc = t / NS;
        sal[t] = fmaxf(c_sign[cc] * (xs[t] - smean[cc]), 0.0f);
    }
    __syncthreads();

    if (t < NS) {
        tmp[t] = sal[t]        * Pcol[0] + sal[NS + t]   * Pcol[1]
               + sal[2*NS + t] * Pcol[2] + sal[3*NS + t] * Pcol[3]
               + sal[4*NS + t] * Pcol[4] + sal[5*NS + t] * Pcol[5];
    }
    __syncthreads();

    if (t < NS) {
        const int ty = t / POOL, tx = t - ty * POOL;
        float acc = 0.f;
        int s = 0;
        #pragma unroll
        for (int sy = 0; sy < POOL; ++sy) {
            const float dy2 = (float)((sy - ty) * (sy - ty));
            #pragma unroll
            for (int sx = 0; sx < POOL; ++sx, ++s) {
                const float dx = (float)(sx - tx);
                acc += __expf(-(dy2 + dx * dx) * 0.78125f) * tmp[s];
            }
        }
        g[t] = c_sign[d] * fmaxf(acc, 0.0f);
    }
    __syncthreads();

    // ---- features: mean/max/min over 49 values (warp 0) ----
    if (t < 32) {
        float a  = g[t];
        bool hi  = (t + 32) < NS;
        float b2 = hi ? g[t + 32] : 0.f;
        float s  = a + b2;
        float mx = hi ? fmaxf(a, b2) : a;
        float mn = hi ? fminf(a, b2) : a;
        #pragma unroll
        for (int o = 16; o; o >>= 1) {
            s  += __shfl_down_sync(0xffffffffu, s,  o);
            mx  = fmaxf(mx, __shfl_down_sync(0xffffffffu, mx, o));
            mn  = fminf(mn, __shfl_down_sync(0xffffffffu, mn, o));
        }
        if (t == 0) {
            feat_out[b * FEAT + d]         = s * (1.0f / (float)NS);
            feat_out[b * FEAT + C + d]     = mx;
            feat_out[b * FEAT + 2 * C + d] = mn;
        }
    }

    // ---- horizontal interpolation table: hr4[r][c4] (1568 floats) ----
    {
        float* hrows = (float*)hr4;
        for (int i = t; i < POOL * W; i += 448) {
            const int r = i / W, j = i - r * W;
            const float sx = (j + 0.5f) * (1.0f / 32.0f) - 0.5f;
            const float x0f = floorf(sx);
            const float fx = sx - x0f;
            const int x0 = max(0, min(6, (int)x0f));
            const int x1 = max(0, min(6, (int)x0f + 1));
            const float a = g[r * POOL + x0];
            hrows[r * W + j] = a + fx * (g[r * POOL + x1] - a);
        }
    }
    __syncthreads();

    // ---- vertical pass: 8 row-segments with constant (y0,y1) ----
    // seg 0: rows 0..15   (y0=y1=0)      seg 7: rows 208..223 (y0=y1=6)
    // seg s in 1..6: rows 32s-16 .. 32s+15 (y0=s-1, y1=s), fy = 1/64 + r/32
    {
        const int s  = t / W4;           // 0..7
        const int c4 = t - s * W4;       // 0..55
        const bool edge = (s == 0) | (s == 7);
        const int y0 = (s == 0) ? 0 : (s - 1);
        const int y1 = (s == 7) ? 6 : s;
        const int row0 = (s == 0) ? 0 : (32 * s - 16);
        const int n = edge ? 16 : 32;

        const float4 a = hr4[y0 * W4 + c4];
        const float4 bb = hr4[y1 * W4 + c4];
        const float dxv = bb.x - a.x, dyv = bb.y - a.y;
        const float dzv = bb.z - a.z, dwv = bb.w - a.w;

        float4* __restrict__ o = (float4*)(out + (size_t)bc * HWSZ) + row0 * W4 + c4;
        #pragma unroll
        for (int r = 0; r < 32; ++r) {
            if (r < n) {
                const float fy = 0.015625f + (float)r * 0.03125f;  // const per r
                float4 v;
                v.x = fmaf(fy, dxv, a.x);
                v.y = fmaf(fy, dyv, a.y);
                v.z = fmaf(fy, dzv, a.z);
                v.w = fmaf(fy, dwv, a.w);
                __stcs(&o[r * W4], v);
            }
        }
    }
}

// ---------------------------------------------------------------------------
extern "C" void kernel_launch(void* const* d_in, const int* in_sizes, int n_in,
                              void* d_out, int out_size)
{
    const float* x       = (const float*)d_in[0];   // (128,6,224,224) f32
    const float* P_delta = (const float*)d_in[1];   // (6,6) f32
    float* out = (float*)d_out;                     // [B*18 | B*C*H*W]

    gate_pool_kernel<<<BC, 256>>>(x);
    graph_upsample_kernel<<<BC, 448>>>(P_delta, out, out + (size_t)B * FEAT);
}

// round 7
// speedup vs baseline: 1.0905x; 1.0905x over previous
#include <cuda_runtime.h>
#include <cuda_fp16.h>
#include <math.h>

#define B 128
#define C 6
#define H 224
#define W 224
#define HWSZ (H*W)          // 50176
#define HW4 (HWSZ/4)        // 12544
#define POOL 7
#define NS (POOL*POOL)      // 49
#define BC (B*C)            // 768
#define CS (C*NS)           // 294
#define FEAT (3*C)          // 18
#define W4 (W/4)            // 56 float4 per row
#define WH2 (W/2)           // 112 half2 per row

__device__ float g_pooled[BC * NS];

__constant__ float c_prior[36] = {
    1.0f,  0.0f,  0.6f,  0.0f, -2.0f, 0.0f,
    0.0f,  1.0f,  0.6f,  0.0f,  0.0f, 0.0f,
    0.1f,  0.1f,  0.5f,  0.0f,  0.0f, 0.0f,
    0.0f,  0.0f,  0.0f,  1.0f,  0.0f, 0.0f,
    0.0f,  0.0f,  0.0f,  0.0f,  1.0f, 0.2f,
    0.0f, -0.6f, -0.6f, -0.6f,  0.6f, 1.0f
};
__constant__ float c_sign[6] = {1.f, -1.f, 1.f, -1.f, 1.f, 1.f};

__device__ __forceinline__ unsigned tanh_h2u(unsigned x) {
    unsigned y;
    asm("tanh.approx.f16x2 %0, %1;" : "=r"(y) : "r"(x));
    return y;
}
__device__ __forceinline__ unsigned h2u(__half2 h) {
    return *(unsigned*)&h;
}
__device__ __forceinline__ __half2 u2h(unsigned u) {
    return *(__half2*)&u;
}

// ---------------------------------------------------------------------------
// Kernel 1: per-(b,c) channel, single DRAM read.
//   pass 1: stream 200KB fp32 from DRAM -> fp32 stats + fp16 shadow in smem.
//   pass 2: half2 gate (HFMA2 + tanh.approx.f16x2) + 32x32 pool from smem.
// smem = 100KB fp16 tile -> 2 blocks/SM: neighbor blocks overlap phases.
// sigmoid((x-mean)/std/0.5) pooled = 0.5 + mean(tanh((x-mean)/std))/2
// ---------------------------------------------------------------------------
__global__ __launch_bounds__(512, 2)
void gate_pool_kernel(const float* __restrict__ x)
{
    extern __shared__ __align__(16) __half2 sh2[];   // 25088 half2 = 100352 B
    __shared__ float ra[16], rb[16];
    __shared__ float s_inv, s_ofs;

    const int bc = blockIdx.x;
    const float4* __restrict__ xin = (const float4*)(x + (size_t)bc * HWSZ);
    uint2* __restrict__ s64 = (uint2*)sh2;

    // ---- pass 1: stats + fp16 pack ----
    float sum = 0.f, sq = 0.f;
    #pragma unroll 4
    for (int i = threadIdx.x; i < HW4; i += 512) {
        float4 v = xin[i];
        sum += (v.x + v.y) + (v.z + v.w);
        sq  += (v.x*v.x + v.y*v.y) + (v.z*v.z + v.w*v.w);
        uint2 u;
        u.x = h2u(__floats2half2_rn(v.x, v.y));
        u.y = h2u(__floats2half2_rn(v.z, v.w));
        s64[i] = u;
    }

    const int warp = threadIdx.x >> 5, lane = threadIdx.x & 31;
    #pragma unroll
    for (int o = 16; o; o >>= 1) {
        sum += __shfl_down_sync(0xffffffffu, sum, o);
        sq  += __shfl_down_sync(0xffffffffu, sq,  o);
    }
    if (lane == 0) { ra[warp] = sum; rb[warp] = sq; }
    __syncthreads();                       // also fences fp16 tile
    if (warp == 0) {
        sum = (lane < 16) ? ra[lane] : 0.f;
        sq  = (lane < 16) ? rb[lane] : 0.f;
        #pragma unroll
        for (int o = 8; o; o >>= 1) {
            sum += __shfl_down_sync(0xffffffffu, sum, o);
            sq  += __shfl_down_sync(0xffffffffu, sq,  o);
        }
        if (lane == 0) {
            const float invN = 1.0f / (float)HWSZ;
            float mean = sum * invN;
            float var = (sq - sum * sum * invN) * (1.0f / (float)(HWSZ - 1));
            var = fmaxf(var, 0.0f);
            float inv_std = 1.0f / (sqrtf(var) + 1e-5f);  // tanh arg = (x-mean)/std
            s_inv = inv_std;
            s_ofs = -mean * inv_std;
        }
    }
    __syncthreads();
    const __half2 s2h = __float2half2_rn(s_inv);
    const __half2 o2h = __float2half2_rn(s_ofs);

    // ---- pass 2: gate + pool from smem fp16 ----
    // warp per window; lane = (row-pair r2, half2-col c16). 16 row-pair iters.
    const int r2  = lane >> 4;       // 0..1
    const int c16 = lane & 15;       // 0..15 half2 within 32-wide window row
    for (int win = warp; win < NS; win += 16) {
        const int py = win / POOL, px = win - py * POOL;
        const __half2* __restrict__ basep =
            sh2 + (py * 32 + r2) * WH2 + px * 16 + c16;
        __half2 acc = __floats2half2_rn(0.f, 0.f);
        #pragma unroll
        for (int rp = 0; rp < 16; ++rp) {        // rows r2, r2+2, ..., r2+30
            __half2 hx = basep[rp * 2 * WH2];
            __half2 z = __hfma2(hx, s2h, o2h);
            acc = __hadd2(acc, u2h(tanh_h2u(h2u(z))));   // |acc| <= 16
        }
        float2 f = __half22float2(acc);
        float facc = f.x + f.y;
        #pragma unroll
        for (int o = 16; o; o >>= 1) facc += __shfl_down_sync(0xffffffffu, facc, o);
        if (lane == 0) g_pooled[bc * NS + win] = facc * (1.0f / 2048.0f) + 0.5f;
    }
}

// ---------------------------------------------------------------------------
// Kernel 2 (fused): graph mixing + feature pooling + structured upsample.
// 448 threads: thread = (segment s in 0..7, float4-column c4 in 0..55).
// ---------------------------------------------------------------------------
__global__ __launch_bounds__(448)
void graph_upsample_kernel(const float* __restrict__ P_delta,
                           float* __restrict__ feat_out,
                           float* __restrict__ out)
{
    __shared__ float xs[CS], sal[CS], tmp[NS];
    __shared__ float Pcol[C], smean[C];
    __shared__ __align__(16) float g[52];
    __shared__ __align__(16) float4 hr4[POOL * W4];   // 7 x 56 float4

    const int bc = blockIdx.x;
    const int b = bc / C, d = bc - b * C;
    const int t = threadIdx.x;

    for (int i = t; i < CS; i += 448) xs[i] = g_pooled[b * CS + i];
    if (t < C) Pcol[t] = c_prior[t * 6 + d] + 0.2f * tanhf(P_delta[t * 6 + d]);
    __syncthreads();

    if (t < C) {
        float m = 0.f;
        #pragma unroll
        for (int s = 0; s < NS; ++s) m += xs[t * NS + s];
        smean[t] = m * (1.0f / (float)NS);
    }
    __syncthreads();

    if (t < CS) {
        const int cc = t / NS;
        sal[t] = fmaxf(c_sign[cc] * (xs[t] - smean[cc]), 0.0f);
    }
    __syncthreads();

    if (t < NS) {
        tmp[t] = sal[t]        * Pcol[0] + sal[NS + t]   * Pcol[1]
               + sal[2*NS + t] * Pcol[2] + sal[3*NS + t] * Pcol[3]
               + sal[4*NS + t] * Pcol[4] + sal[5*NS + t] * Pcol[5];
    }
    __syncthreads();

    if (t < NS) {
        const int ty = t / POOL, tx = t - ty * POOL;
        float acc = 0.f;
        int s = 0;
        #pragma unroll
        for (int sy = 0; sy < POOL; ++sy) {
            const float dy2 = (float)((sy - ty) * (sy - ty));
            #pragma unroll
            for (int sx = 0; sx < POOL; ++sx, ++s) {
                const float dx = (float)(sx - tx);
                acc += __expf(-(dy2 + dx * dx) * 0.78125f) * tmp[s];
            }
        }
        g[t] = c_sign[d] * fmaxf(acc, 0.0f);
    }
    __syncthreads();

    if (t < 32) {
        float a  = g[t];
        bool hi  = (t + 32) < NS;
        float b2 = hi ? g[t + 32] : 0.f;
        float s  = a + b2;
        float mx = hi ? fmaxf(a, b2) : a;
        float mn = hi ? fminf(a, b2) : a;
        #pragma unroll
        for (int o = 16; o; o >>= 1) {
            s  += __shfl_down_sync(0xffffffffu, s,  o);
            mx  = fmaxf(mx, __shfl_down_sync(0xffffffffu, mx, o));
            mn  = fminf(mn, __shfl_down_sync(0xffffffffu, mn, o));
        }
        if (t == 0) {
            feat_out[b * FEAT + d]         = s * (1.0f / (float)NS);
            feat_out[b * FEAT + C + d]     = mx;
            feat_out[b * FEAT + 2 * C + d] = mn;
        }
    }

    {
        float* hrows = (float*)hr4;
        for (int i = t; i < POOL * W; i += 448) {
            const int r = i / W, j = i - r * W;
            const float sx = (j + 0.5f) * (1.0f / 32.0f) - 0.5f;
            const float x0f = floorf(sx);
            const float fx = sx - x0f;
            const int x0 = max(0, min(6, (int)x0f));
            const int x1 = max(0, min(6, (int)x0f + 1));
            const float a = g[r * POOL + x0];
            hrows[r * W + j] = a + fx * (g[r * POOL + x1] - a);
        }
    }
    __syncthreads();

    {
        const int s  = t / W4;           // 0..7
        const int c4 = t - s * W4;       // 0..55
        const bool edge = (s == 0) | (s == 7);
        const int y0 = (s == 0) ? 0 : (s - 1);
        const int y1 = (s == 7) ? 6 : s;
        const int row0 = (s == 0) ? 0 : (32 * s - 16);
        const int n = edge ? 16 : 32;

        const float4 a = hr4[y0 * W4 + c4];
        const float4 bb = hr4[y1 * W4 + c4];
        const float dxv = bb.x - a.x, dyv = bb.y - a.y;
        const float dzv = bb.z - a.z, dwv = bb.w - a.w;

        float4* __restrict__ o = (float4*)(out + (size_t)bc * HWSZ) + row0 * W4 + c4;
        #pragma unroll
        for (int r = 0; r < 32; ++r) {
            if (r < n) {
                const float fy = 0.015625f + (float)r * 0.03125f;
                float4 v;
                v.x = fmaf(fy, dxv, a.x);
                v.y = fmaf(fy, dyv, a.y);
                v.z = fmaf(fy, dzv, a.z);
                v.w = fmaf(fy, dwv, a.w);
                __stcs(&o[r * W4], v);
            }
        }
    }
}

// ---------------------------------------------------------------------------
extern "C" void kernel_launch(void* const* d_in, const int* in_sizes, int n_in,
                              void* d_out, int out_size)
{
    const float* x       = (const float*)d_in[0];   // (128,6,224,224) f32
    const float* P_delta = (const float*)d_in[1];   // (6,6) f32
    float* out = (float*)d_out;                     // [B*18 | B*C*H*W]

    const int SMEM1 = HW4 * 8;   // 100352 B fp16 tile
    cudaFuncSetAttribute(gate_pool_kernel,
                         cudaFuncAttributeMaxDynamicSharedMemorySize, SMEM1);

    gate_pool_kernel<<<BC, 512, SMEM1>>>(x);
    graph_upsample_kernel<<<BC, 448>>>(P_delta, out, out + (size_t)B * FEAT);
}